// round 11
// baseline (speedup 1.0000x reference)
#include <cuda_runtime.h>
#include <math.h>

#define H      1024
#define H4     (H/4)          // 256 float4 per H row
#define HH2    512
#define V      32000
#define WIN    129
#define NB     148
#define NT     1024
#define NWRP   (NB * 32)       // 4736 warps
#define SMAX   4096
#define NEG    -1e30f
#define CHUNK  217             // ceil(V/NB)
#define PF_IT  8               // prefetch rows per idle warp per LSTM phase

// ---------------- persistent scratch (no allocation allowed) ----------------
__device__ float g_t1[HH2];          // tanh(att_fc1)
__device__ float g_sc[SMAX];         // full-sequence raw scores
__device__ float g_ctx[H];           // attention context (atomicAdd target)
__device__ float g_pm[NB];           // per-block logit max
__device__ float g_ps[NB];           // per-block logit expsum
__device__ unsigned g_cnt;           // barrier arrival counter
__device__ volatile unsigned g_sense;// barrier sense flag

// ---------------- helpers ----------------
__device__ __forceinline__ float dot4(float4 a, float4 b) {
    return fmaf(a.x, b.x, fmaf(a.y, b.y, fmaf(a.z, b.z, a.w * b.w)));
}
__device__ __forceinline__ float warpSum(float v) {
    #pragma unroll
    for (int o = 16; o > 0; o >>= 1) v += __shfl_xor_sync(0xffffffffu, v, o);
    return v;
}
__device__ __forceinline__ float warpMax(float v) {
    #pragma unroll
    for (int o = 16; o > 0; o >>= 1) v = fmaxf(v, __shfl_xor_sync(0xffffffffu, v, o));
    return v;
}
__device__ __forceinline__ float sigm(float x) { return 1.f / (1.f + expf(-x)); }
__device__ __forceinline__ void prefetchL2(const void* p) {
    asm volatile("prefetch.global.L2 [%0];" :: "l"(p));
}

// ---------------- grid barrier (sense-reversing, all NB blocks) ----------------
__device__ __forceinline__ void gbar() {
    __syncthreads();
    if (threadIdx.x == 0) {
        unsigned my = g_sense;                 // volatile read
        __threadfence();                       // release prior writes
        if (atomicAdd(&g_cnt, 1u) == NB - 1u) {
            atomicExch(&g_cnt, 0u);            // reset for next barrier
            __threadfence();
            g_sense = my ^ 1u;                 // release
        } else {
            while (g_sense == my) { }          // volatile poll
            __threadfence();                   // acquire
        }
    }
    __syncthreads();
}

struct Shm {
    float gate[28];      // 7 rows x 4 gates
    float red[32];
    float sarr[WIN];
    float aarr[WIN];
    float mr[256];
    float sr[256];
    float p;
    int   ws, we;
    float mx, sum;
};

// ---------------- LSTM layer: 28 warps/block, 4 gate-warps per row ----------------
// Warps 28-31 are idle for the matvec: they prefetch fc2 weights into L2
// (fire-and-forget) to fill the otherwise-idle DRAM window on graph replays.
__device__ __forceinline__ void lstm_layer(
    const float4* __restrict__ x4, const float4* __restrict__ h4,
    const float* __restrict__ cprev,
    const float* __restrict__ wih, const float* __restrict__ whh,
    const float* __restrict__ bih, const float* __restrict__ bhh,
    float* __restrict__ hout, float* __restrict__ cout,
    const float* __restrict__ f2w, int phase,
    int bid, int wid, int lane, Shm& sm)
{
    int q = wid >> 2;            // local row 0..7
    int gate = wid & 3;
    int r = bid * 7 + q;
    if (q < 7 && r < H) {
        const float4* wi = (const float4*)wih + ((size_t)gate * H + r) * H4;
        const float4* wh = (const float4*)whh + ((size_t)gate * H + r) * H4;
        float acc = 0.f;
        #pragma unroll
        for (int k = 0; k < 8; k++) {
            int i = lane + 32 * k;
            acc += dot4(wi[i], x4[i]) + dot4(wh[i], h4[i]);
        }
        acc = warpSum(acc);
        if (lane == 0) sm.gate[q * 4 + gate] = acc;
    } else if (q == 7) {
        // idle warp: prefetch a 32KB slice of fc2 weights into L2
        int iw = (phase * NB + bid) * 4 + (wid - 28);      // 0..1183
        const char* base = (const char*)f2w + (size_t)iw * (PF_IT * 4096) + lane * 128;
        #pragma unroll
        for (int it = 0; it < PF_IT; it++)
            prefetchL2(base + (size_t)it * 4096);
    }
    __syncthreads();
    int t = threadIdx.x;
    if (t < 7) {
        int r2 = bid * 7 + t;
        if (r2 < H) {
            float gi = sm.gate[t * 4 + 0] + bih[r2        ] + bhh[r2        ];
            float gf = sm.gate[t * 4 + 1] + bih[r2 +     H] + bhh[r2 +     H];
            float gg = sm.gate[t * 4 + 2] + bih[r2 + 2 * H] + bhh[r2 + 2 * H];
            float go = sm.gate[t * 4 + 3] + bih[r2 + 3 * H] + bhh[r2 + 3 * H];
            float c  = sigm(gf) * cprev[r2] + sigm(gi) * tanhf(gg);
            cout[r2] = c;
            hout[r2] = sigm(go) * tanhf(c);
        }
    }
}

// ---------------- the megakernel ----------------
__global__ void __launch_bounds__(NT, 1) decoder_mega(
    const float* __restrict__ enc, const int* __restrict__ word,
    const float* __restrict__ h0,  const float* __restrict__ c0,
    const float* __restrict__ emb,
    const float* __restrict__ wih, const float* __restrict__ whh,
    const float* __restrict__ bih, const float* __restrict__ bhh,
    const float* __restrict__ a1w, const float* __restrict__ a1b,
    const float* __restrict__ a2w, const float* __restrict__ a2b,
    const float* __restrict__ f1w, const float* __restrict__ f1b,
    const float* __restrict__ f2w, const float* __restrict__ f2b,
    float* __restrict__ dout, int S)
{
    __shared__ Shm sm;
    const int tid = threadIdx.x, lane = tid & 31, wid = tid >> 5;
    const int bid = blockIdx.x;
    const int gw  = bid * 32 + wid;
    const float Sf = (float)S;

    float* y    = dout;              // [V]
    float* fco  = y   + V;           // [H]
    float* hn   = fco + H;           // [2,H]
    float* cn   = hn  + 2 * H;       // [2,H]
    float* aout = cn  + 2 * H;       // [WIN]

    // ---- phase 0: LSTM layer 0 (x = embedding[word]) ----
    {
        const float4* x4 = (const float4*)(emb + (size_t)word[0] * H);
        const float4* h4 = (const float4*)h0;
        lstm_layer(x4, h4, c0, wih, whh, bih, bhh, hn, cn,
                   f2w, 0, bid, wid, lane, sm);
    }
    gbar();

    // ---- phase 1: LSTM layer 1 (x = h of layer 0) ----
    {
        const float4* x4 = (const float4*)hn;
        const float4* h4 = (const float4*)(h0 + H);
        lstm_layer(x4, h4, c0 + H, wih + 4 * H * H, whh + 4 * H * H,
                   bih + 4 * H, bhh + 4 * H, hn + H, cn + H,
                   f2w, 1, bid, wid, lane, sm);
    }
    gbar();

    const float* ht = hn + H;
    const float4* ht4 = (const float4*)ht;

    // ---- phase 2: att_fc1 (512 rows) + full-sequence scores + scratch reset ----
    if (gw < HH2) {
        const float4* w4 = (const float4*)a1w + (size_t)gw * H4;
        float acc = 0.f;
        #pragma unroll
        for (int k = 0; k < 8; k++) { int i = lane + 32 * k; acc += dot4(w4[i], ht4[i]); }
        acc = warpSum(acc);
        if (lane == 0) g_t1[gw] = tanhf(acc + a1b[gw]);
    } else {
        int s = gw - HH2;
        int slim = (S < SMAX) ? S : SMAX;
        if (s < slim) {
            const float4* e4 = (const float4*)(enc + (size_t)s * H);
            float acc = 0.f;
            #pragma unroll
            for (int k = 0; k < 8; k++) { int i = lane + 32 * k; acc += dot4(e4[i], ht4[i]); }
            acc = warpSum(acc);
            if (lane == 0) g_sc[s] = acc;
        }
    }
    if (bid == NB - 1) g_ctx[tid] = 0.f;
    gbar();

    // ---- phase 3: redundant p + window softmax; distributed ctx ----
    {
        float part = (tid < HH2) ? g_t1[tid] * a2w[tid] : 0.f;
        part = warpSum(part);
        if (lane == 0) sm.red[wid] = part;
        __syncthreads();
        if (tid == 0) {
            float s = a2b[0];
            #pragma unroll
            for (int i = 0; i < 32; i++) s += sm.red[i];
            float p = Sf * sigm(s);
            sm.p  = p;
            sm.ws = (int)rintf(fmaxf(p - 64.f, 0.f));
            sm.we = (int)rintf(fminf(p + 64.f, Sf - 1.f));
        }
        __syncthreads();
        int ws = sm.ws, we = sm.we;
        if (tid < WIN) {
            int idx = ws + tid;
            int ic  = min(idx, S - 1);
            sm.sarr[tid] = (idx <= we) ? g_sc[ic] : NEG;
        }
        __syncthreads();
        if (tid < 32) {
            float m = NEG;
            for (int i = lane; i < WIN; i += 32) m = fmaxf(m, sm.sarr[i]);
            m = warpMax(m);
            float e = 0.f;
            for (int i = lane; i < WIN; i += 32) e += expf(sm.sarr[i] - m);
            e = warpSum(e);
            if (lane == 0) { sm.mx = m; sm.sum = e; }
        }
        __syncthreads();
        if (tid < WIN) {
            int idx = ws + tid;
            float a = expf(sm.sarr[tid] - sm.mx) / sm.sum;
            float gss = expf(((float)idx - sm.p) * (1.f / 2048.f));
            a = (idx <= we) ? a * gss : 0.f;
            sm.aarr[tid] = a;
            if (bid == 0) aout[tid] = a;
        }
        __syncthreads();
        if (bid < WIN) {                 // block b accumulates window row b
            float a = sm.aarr[bid];
            int idx = min(sm.ws + bid, S - 1);
            atomicAdd(&g_ctx[tid], a * enc[(size_t)idx * H + tid]);
        }
    }
    gbar();

    // ---- phase 4: fc1 (1024 rows x 2048), rows spread over all blocks ----
    {
        int r = wid * NB + bid;
        if (wid < 7 && r < H) {
            const float4* w4 = (const float4*)f1w + (size_t)r * (2 * H4);
            const float4* c4 = (const float4*)g_ctx;
            float acc = 0.f;
            #pragma unroll
            for (int k = 0; k < 8; k++) { int i = lane + 32 * k; acc += dot4(w4[i      ], c4[i]); }
            #pragma unroll
            for (int k = 0; k < 8; k++) { int i = lane + 32 * k; acc += dot4(w4[i + 256], ht4[i]); }
            acc = warpSum(acc);
            if (lane == 0) fco[r] = tanhf(acc + f1b[r]);
        }
    }
    gbar();

    // ---- phase 5: fc2 (32000 x 1024) — R2 loop, STREAMING loads (__ldcs) ----
    // Evict-first reads keep the LSTM/fc1/enc set (~94MB) L2-resident across
    // graph replays; prefetched head of f2w (~38MB) hits L2 here.
    {
        const float4* x4 = (const float4*)fco;
        for (int r = gw; r < V; r += NWRP) {
            const float4* w4 = (const float4*)f2w + (size_t)r * H4;
            float acc = 0.f;
            #pragma unroll
            for (int k = 0; k < 8; k++) {
                int i = lane + 32 * k;
                acc += dot4(__ldcs(w4 + i), x4[i]);
            }
            acc = warpSum(acc);
            if (lane == 0) y[r] = acc + f2b[r];
        }
    }
    gbar();

    // ---- phase 6: per-block (max, expsum) over own 217-logit chunk ----
    {
        int i = bid * CHUNK + tid;
        bool ok = (tid < CHUNK) && (i < V);
        float v = ok ? y[i] : NEG;
        float m = warpMax(v);
        if (lane == 0) sm.red[wid] = m;
        __syncthreads();
        if (tid == 0) {
            float mm = sm.red[0];
            #pragma unroll
            for (int k = 1; k < 32; k++) mm = fmaxf(mm, sm.red[k]);
            sm.mx = mm;
        }
        __syncthreads();
        float mx = sm.mx;
        float e = ok ? expf(v - mx) : 0.f;
        e = warpSum(e);
        __syncthreads();
        if (lane == 0) sm.red[wid] = e;
        __syncthreads();
        if (tid == 0) {
            float ss = 0.f;
            #pragma unroll
            for (int k = 0; k < 32; k++) ss += sm.red[k];
            g_pm[bid] = mx; g_ps[bid] = ss;
        }
    }
    gbar();

    // ---- phase 7: combine 148 partials (fixed tree); subtract lse over chunk ----
    {
        if (tid < 256) {
            if (tid < NB) { sm.mr[tid] = g_pm[tid]; sm.sr[tid] = g_ps[tid]; }
            else          { sm.mr[tid] = NEG;       sm.sr[tid] = 0.f; }
        }
        __syncthreads();
        for (int off = 128; off > 0; off >>= 1) {
            if (tid < off) {
                float m1 = sm.mr[tid], m2 = sm.mr[tid + off];
                float m = fmaxf(m1, m2);
                sm.sr[tid] = sm.sr[tid] * expf(m1 - m) + sm.sr[tid + off] * expf(m2 - m);
                sm.mr[tid] = m;
            }
            __syncthreads();
        }
        float lse = sm.mr[0] + logf(sm.sr[0]);
        int i = bid * CHUNK + tid;
        if (tid < CHUNK && i < V) y[i] -= lse;
    }
}

// ---------------- launch ----------------
extern "C" void kernel_launch(void* const* d_in, const int* in_sizes, int n_in,
                              void* d_out, int out_size)
{
    const float* enc  = (const float*)d_in[1];
    const int*   word = (const int*)  d_in[2];
    const float* h0   = (const float*)d_in[3];
    const float* c0   = (const float*)d_in[4];
    const float* emb  = (const float*)d_in[5];
    const float* wih  = (const float*)d_in[6];
    const float* whh  = (const float*)d_in[7];
    const float* bih  = (const float*)d_in[8];
    const float* bhh  = (const float*)d_in[9];
    const float* a1w  = (const float*)d_in[10];
    const float* a1b  = (const float*)d_in[11];
    const float* a2w  = (const float*)d_in[12];
    const float* a2b  = (const float*)d_in[13];
    const float* f1w  = (const float*)d_in[14];
    const float* f1b  = (const float*)d_in[15];
    const float* f2w  = (const float*)d_in[16];
    const float* f2b  = (const float*)d_in[17];

    int S = in_sizes[1] / H;

    decoder_mega<<<NB, NT>>>(enc, word, h0, c0, emb, wih, whh, bih, bhh,
                             a1w, a1b, a2w, a2b, f1w, f1b, f2w, f2b,
                             (float*)d_out, S);
}

// round 12
// speedup vs baseline: 1.0224x; 1.0224x over previous
#include <cuda_runtime.h>
#include <math.h>

#define H      1024
#define H4     (H/4)          // 256 float4 per H row
#define HH2    512
#define V      32000
#define WIN    129
#define NB     148
#define NT     1024
#define NWRP   (NB * 32)       // 4736 warps
#define SMAX   4096
#define NEG    -1e30f
#define CHUNK  217             // ceil(V/NB)
#define FC2_HEAD 6016          // rows of f2w kept L2-resident (24.6 MB)

// ---------------- persistent scratch (no allocation allowed) ----------------
__device__ float g_t1[HH2];          // tanh(att_fc1)
__device__ float g_sc[SMAX];         // full-sequence raw scores
__device__ float g_ctx[H];           // attention context (atomicAdd target)
__device__ float g_pm[NB];           // per-block logit max
__device__ float g_ps[NB];           // per-block logit expsum
__device__ unsigned g_cnt;           // barrier arrival counter
__device__ volatile unsigned g_sense;// barrier sense flag

// ---------------- helpers ----------------
__device__ __forceinline__ float dot4(float4 a, float4 b) {
    return fmaf(a.x, b.x, fmaf(a.y, b.y, fmaf(a.z, b.z, a.w * b.w)));
}
__device__ __forceinline__ float warpSum(float v) {
    #pragma unroll
    for (int o = 16; o > 0; o >>= 1) v += __shfl_xor_sync(0xffffffffu, v, o);
    return v;
}
__device__ __forceinline__ float warpMax(float v) {
    #pragma unroll
    for (int o = 16; o > 0; o >>= 1) v = fmaxf(v, __shfl_xor_sync(0xffffffffu, v, o));
    return v;
}
__device__ __forceinline__ float sigm(float x) { return 1.f / (1.f + expf(-x)); }

// ---------------- grid barrier (sense-reversing, all NB blocks) ----------------
__device__ __forceinline__ void gbar() {
    __syncthreads();
    if (threadIdx.x == 0) {
        unsigned my = g_sense;                 // volatile read
        __threadfence();                       // release prior writes
        if (atomicAdd(&g_cnt, 1u) == NB - 1u) {
            atomicExch(&g_cnt, 0u);            // reset for next barrier
            __threadfence();
            g_sense = my ^ 1u;                 // release
        } else {
            while (g_sense == my) { }          // volatile poll
            __threadfence();                   // acquire
        }
    }
    __syncthreads();
}

struct Shm {
    float gate[28];      // 7 rows x 4 gates
    float red[32];
    float sarr[WIN];
    float aarr[WIN];
    float mr[256];
    float sr[256];
    float p;
    int   ws, we;
    float mx, sum;
};

// ---------------- LSTM layer: 28 warps/block, 4 gate-warps per row (R2 verbatim) ----------------
__device__ __forceinline__ void lstm_layer(
    const float4* __restrict__ x4, const float4* __restrict__ h4,
    const float* __restrict__ cprev,
    const float* __restrict__ wih, const float* __restrict__ whh,
    const float* __restrict__ bih, const float* __restrict__ bhh,
    float* __restrict__ hout, float* __restrict__ cout,
    int bid, int wid, int lane, Shm& sm)
{
    int q = wid >> 2;            // local row 0..7
    int gate = wid & 3;
    int r = bid * 7 + q;
    if (q < 7 && r < H) {
        const float4* wi = (const float4*)wih + ((size_t)gate * H + r) * H4;
        const float4* wh = (const float4*)whh + ((size_t)gate * H + r) * H4;
        float acc = 0.f;
        #pragma unroll
        for (int k = 0; k < 8; k++) {
            int i = lane + 32 * k;
            acc += dot4(wi[i], x4[i]) + dot4(wh[i], h4[i]);
        }
        acc = warpSum(acc);
        if (lane == 0) sm.gate[q * 4 + gate] = acc;
    }
    __syncthreads();
    int t = threadIdx.x;
    if (t < 7) {
        int r2 = bid * 7 + t;
        if (r2 < H) {
            float gi = sm.gate[t * 4 + 0] + bih[r2        ] + bhh[r2        ];
            float gf = sm.gate[t * 4 + 1] + bih[r2 +     H] + bhh[r2 +     H];
            float gg = sm.gate[t * 4 + 2] + bih[r2 + 2 * H] + bhh[r2 + 2 * H];
            float go = sm.gate[t * 4 + 3] + bih[r2 + 3 * H] + bhh[r2 + 3 * H];
            float c  = sigm(gf) * cprev[r2] + sigm(gi) * tanhf(gg);
            cout[r2] = c;
            hout[r2] = sigm(go) * tanhf(c);
        }
    }
}

// ---------------- the megakernel ----------------
__global__ void __launch_bounds__(NT, 1) decoder_mega(
    const float* __restrict__ enc, const int* __restrict__ word,
    const float* __restrict__ h0,  const float* __restrict__ c0,
    const float* __restrict__ emb,
    const float* __restrict__ wih, const float* __restrict__ whh,
    const float* __restrict__ bih, const float* __restrict__ bhh,
    const float* __restrict__ a1w, const float* __restrict__ a1b,
    const float* __restrict__ a2w, const float* __restrict__ a2b,
    const float* __restrict__ f1w, const float* __restrict__ f1b,
    const float* __restrict__ f2w, const float* __restrict__ f2b,
    float* __restrict__ dout, int S)
{
    __shared__ Shm sm;
    const int tid = threadIdx.x, lane = tid & 31, wid = tid >> 5;
    const int bid = blockIdx.x;
    const int gw  = bid * 32 + wid;
    const float Sf = (float)S;

    float* y    = dout;              // [V]
    float* fco  = y   + V;           // [H]
    float* hn   = fco + H;           // [2,H]
    float* cn   = hn  + 2 * H;       // [2,H]
    float* aout = cn  + 2 * H;       // [WIN]

    // ---- phase 0: LSTM layer 0 (x = embedding[word]) ----
    {
        const float4* x4 = (const float4*)(emb + (size_t)word[0] * H);
        const float4* h4 = (const float4*)h0;
        lstm_layer(x4, h4, c0, wih, whh, bih, bhh, hn, cn, bid, wid, lane, sm);
    }
    gbar();

    // ---- phase 1: LSTM layer 1 (x = h of layer 0) ----
    {
        const float4* x4 = (const float4*)hn;
        const float4* h4 = (const float4*)(h0 + H);
        lstm_layer(x4, h4, c0 + H, wih + 4 * H * H, whh + 4 * H * H,
                   bih + 4 * H, bhh + 4 * H, hn + H, cn + H, bid, wid, lane, sm);
    }
    gbar();

    const float* ht = hn + H;
    const float4* ht4 = (const float4*)ht;

    // ---- phase 2: att_fc1 (512 rows) + full-sequence scores + scratch reset ----
    if (gw < HH2) {
        const float4* w4 = (const float4*)a1w + (size_t)gw * H4;
        float acc = 0.f;
        #pragma unroll
        for (int k = 0; k < 8; k++) { int i = lane + 32 * k; acc += dot4(w4[i], ht4[i]); }
        acc = warpSum(acc);
        if (lane == 0) g_t1[gw] = tanhf(acc + a1b[gw]);
    } else {
        int s = gw - HH2;
        int slim = (S < SMAX) ? S : SMAX;
        if (s < slim) {
            const float4* e4 = (const float4*)(enc + (size_t)s * H);
            float acc = 0.f;
            #pragma unroll
            for (int k = 0; k < 8; k++) { int i = lane + 32 * k; acc += dot4(e4[i], ht4[i]); }
            acc = warpSum(acc);
            if (lane == 0) g_sc[s] = acc;
        }
    }
    if (bid == NB - 1) g_ctx[tid] = 0.f;
    gbar();

    // ---- phase 3: redundant p + window softmax; distributed ctx ----
    {
        float part = (tid < HH2) ? g_t1[tid] * a2w[tid] : 0.f;
        part = warpSum(part);
        if (lane == 0) sm.red[wid] = part;
        __syncthreads();
        if (tid == 0) {
            float s = a2b[0];
            #pragma unroll
            for (int i = 0; i < 32; i++) s += sm.red[i];
            float p = Sf * sigm(s);
            sm.p  = p;
            sm.ws = (int)rintf(fmaxf(p - 64.f, 0.f));
            sm.we = (int)rintf(fminf(p + 64.f, Sf - 1.f));
        }
        __syncthreads();
        int ws = sm.ws, we = sm.we;
        if (tid < WIN) {
            int idx = ws + tid;
            int ic  = min(idx, S - 1);
            sm.sarr[tid] = (idx <= we) ? g_sc[ic] : NEG;
        }
        __syncthreads();
        if (tid < 32) {
            float m = NEG;
            for (int i = lane; i < WIN; i += 32) m = fmaxf(m, sm.sarr[i]);
            m = warpMax(m);
            float e = 0.f;
            for (int i = lane; i < WIN; i += 32) e += expf(sm.sarr[i] - m);
            e = warpSum(e);
            if (lane == 0) { sm.mx = m; sm.sum = e; }
        }
        __syncthreads();
        if (tid < WIN) {
            int idx = ws + tid;
            float a = expf(sm.sarr[tid] - sm.mx) / sm.sum;
            float gss = expf(((float)idx - sm.p) * (1.f / 2048.f));
            a = (idx <= we) ? a * gss : 0.f;
            sm.aarr[tid] = a;
            if (bid == 0) aout[tid] = a;
        }
        __syncthreads();
        if (bid < WIN) {                 // block b accumulates window row b
            float a = sm.aarr[bid];
            int idx = min(sm.ws + bid, S - 1);
            atomicAdd(&g_ctx[tid], a * enc[(size_t)idx * H + tid]);
        }
    }
    gbar();

    // ---- phase 4: fc1 (1024 rows x 2048), rows spread over all blocks ----
    {
        int r = wid * NB + bid;
        if (wid < 7 && r < H) {
            const float4* w4 = (const float4*)f1w + (size_t)r * (2 * H4);
            const float4* c4 = (const float4*)g_ctx;
            float acc = 0.f;
            #pragma unroll
            for (int k = 0; k < 8; k++) { int i = lane + 32 * k; acc += dot4(w4[i      ], c4[i]); }
            #pragma unroll
            for (int k = 0; k < 8; k++) { int i = lane + 32 * k; acc += dot4(w4[i + 256], ht4[i]); }
            acc = warpSum(acc);
            if (lane == 0) fco[r] = tanhf(acc + f1b[r]);
        }
    }
    gbar();

    // ---- phase 5: fc2 (32000 x 1024) — resident head (normal LDG) +
    //                streaming tail (__ldcs). Head joins the L2-retained set
    //                across graph replays; tail streams evict-first. ----
    {
        const float4* x4 = (const float4*)fco;
        for (int r = gw; r < V; r += NWRP) {
            const float4* w4 = (const float4*)f2w + (size_t)r * H4;
            float acc = 0.f;
            if (r < FC2_HEAD) {
                #pragma unroll
                for (int k = 0; k < 8; k++) {
                    int i = lane + 32 * k;
                    acc += dot4(w4[i], x4[i]);
                }
            } else {
                #pragma unroll
                for (int k = 0; k < 8; k++) {
                    int i = lane + 32 * k;
                    acc += dot4(__ldcs(w4 + i), x4[i]);
                }
            }
            acc = warpSum(acc);
            if (lane == 0) y[r] = acc + f2b[r];
        }
    }
    gbar();

    // ---- phase 6: per-block (max, expsum) over own 217-logit chunk ----
    {
        int i = bid * CHUNK + tid;
        bool ok = (tid < CHUNK) && (i < V);
        float v = ok ? y[i] : NEG;
        float m = warpMax(v);
        if (lane == 0) sm.red[wid] = m;
        __syncthreads();
        if (tid == 0) {
            float mm = sm.red[0];
            #pragma unroll
            for (int k = 1; k < 32; k++) mm = fmaxf(mm, sm.red[k]);
            sm.mx = mm;
        }
        __syncthreads();
        float mx = sm.mx;
        float e = ok ? expf(v - mx) : 0.f;
        e = warpSum(e);
        __syncthreads();
        if (lane == 0) sm.red[wid] = e;
        __syncthreads();
        if (tid == 0) {
            float ss = 0.f;
            #pragma unroll
            for (int k = 0; k < 32; k++) ss += sm.red[k];
            g_pm[bid] = mx; g_ps[bid] = ss;
        }
    }
    gbar();

    // ---- phase 7: combine 148 partials (fixed tree); subtract lse over chunk ----
    {
        if (tid < 256) {
            if (tid < NB) { sm.mr[tid] = g_pm[tid]; sm.sr[tid] = g_ps[tid]; }
            else          { sm.mr[tid] = NEG;       sm.sr[tid] = 0.f; }
        }
        __syncthreads();
        for (int off = 128; off > 0; off >>= 1) {
            if (tid < off) {
                float m1 = sm.mr[tid], m2 = sm.mr[tid + off];
                float m = fmaxf(m1, m2);
                sm.sr[tid] = sm.sr[tid] * expf(m1 - m) + sm.sr[tid + off] * expf(m2 - m);
                sm.mr[tid] = m;
            }
            __syncthreads();
        }
        float lse = sm.mr[0] + logf(sm.sr[0]);
        int i = bid * CHUNK + tid;
        if (tid < CHUNK && i < V) y[i] -= lse;
    }
}

// ---------------- launch ----------------
extern "C" void kernel_launch(void* const* d_in, const int* in_sizes, int n_in,
                              void* d_out, int out_size)
{
    const float* enc  = (const float*)d_in[1];
    const int*   word = (const int*)  d_in[2];
    const float* h0   = (const float*)d_in[3];
    const float* c0   = (const float*)d_in[4];
    const float* emb  = (const float*)d_in[5];
    const float* wih  = (const float*)d_in[6];
    const float* whh  = (const float*)d_in[7];
    const float* bih  = (const float*)d_in[8];
    const float* bhh  = (const float*)d_in[9];
    const float* a1w  = (const float*)d_in[10];
    const float* a1b  = (const float*)d_in[11];
    const float* a2w  = (const float*)d_in[12];
    const float* a2b  = (const float*)d_in[13];
    const float* f1w  = (const float*)d_in[14];
    const float* f1b  = (const float*)d_in[15];
    const float* f2w  = (const float*)d_in[16];
    const float* f2b  = (const float*)d_in[17];

    int S = in_sizes[1] / H;

    decoder_mega<<<NB, NT>>>(enc, word, h0, c0, emb, wih, whh, bih, bhh,
                             a1w, a1b, a2w, a2b, f1w, f1b, f2w, f2b,
                             (float*)d_out, S);
}

// round 13
// speedup vs baseline: 1.1322x; 1.1074x over previous
#include <cuda_runtime.h>
#include <math.h>

#define H      1024
#define H4     (H/4)          // 256 float4 per H row
#define HH2    512
#define V      32000
#define WIN    129
#define NB     148
#define NT     1024
#define NWRP   (NB * 32)       // 4736 warps
#define SMAX   4096
#define NEG    -1e30f
#define CHUNK  217             // ceil(V/NB); 31 warps x 7 rows
#define FC2_HEAD 2048          // rows of f2w kept L2-resident (8.4 MB)

// ---------------- persistent scratch (no allocation allowed) ----------------
__device__ float g_t1[HH2];          // tanh(att_fc1)
__device__ float g_sc[SMAX];         // full-sequence raw scores
__device__ float g_ctx[H];           // attention context (atomicAdd target)
__device__ float g_pm[NB];           // per-block logit max
__device__ float g_ps[NB];           // per-block logit expsum
__device__ unsigned g_cnt;           // barrier arrival counter
__device__ volatile unsigned g_sense;// barrier sense flag

// ---------------- helpers ----------------
__device__ __forceinline__ float dot4(float4 a, float4 b) {
    return fmaf(a.x, b.x, fmaf(a.y, b.y, fmaf(a.z, b.z, a.w * b.w)));
}
__device__ __forceinline__ float warpSum(float v) {
    #pragma unroll
    for (int o = 16; o > 0; o >>= 1) v += __shfl_xor_sync(0xffffffffu, v, o);
    return v;
}
__device__ __forceinline__ float warpMax(float v) {
    #pragma unroll
    for (int o = 16; o > 0; o >>= 1) v = fmaxf(v, __shfl_xor_sync(0xffffffffu, v, o));
    return v;
}
__device__ __forceinline__ float sigm(float x) { return 1.f / (1.f + expf(-x)); }

// ---------------- grid barrier (sense-reversing, all NB blocks) ----------------
__device__ __forceinline__ void gbar() {
    __syncthreads();
    if (threadIdx.x == 0) {
        unsigned my = g_sense;                 // volatile read
        __threadfence();                       // release prior writes
        if (atomicAdd(&g_cnt, 1u) == NB - 1u) {
            atomicExch(&g_cnt, 0u);            // reset for next barrier
            __threadfence();
            g_sense = my ^ 1u;                 // release
        } else {
            while (g_sense == my) { }          // volatile poll
            __threadfence();                   // acquire
        }
    }
    __syncthreads();
}

struct Shm {
    float gate[28];      // 7 rows x 4 gates
    float red[32];
    float sarr[WIN];
    float aarr[WIN];
    float mr[256];
    float sr[256];
    float lv[CHUNK];     // this block's raw logits
    float p;
    int   ws, we;
    float mx, sum;
};

// ---------------- LSTM layer: 28 warps/block, 4 gate-warps per row (R2 verbatim) ----------------
__device__ __forceinline__ void lstm_layer(
    const float4* __restrict__ x4, const float4* __restrict__ h4,
    const float* __restrict__ cprev,
    const float* __restrict__ wih, const float* __restrict__ whh,
    const float* __restrict__ bih, const float* __restrict__ bhh,
    float* __restrict__ hout, float* __restrict__ cout,
    int bid, int wid, int lane, Shm& sm)
{
    int q = wid >> 2;            // local row 0..7
    int gate = wid & 3;
    int r = bid * 7 + q;
    if (q < 7 && r < H) {
        const float4* wi = (const float4*)wih + ((size_t)gate * H + r) * H4;
        const float4* wh = (const float4*)whh + ((size_t)gate * H + r) * H4;
        float acc = 0.f;
        #pragma unroll
        for (int k = 0; k < 8; k++) {
            int i = lane + 32 * k;
            acc += dot4(wi[i], x4[i]) + dot4(wh[i], h4[i]);
        }
        acc = warpSum(acc);
        if (lane == 0) sm.gate[q * 4 + gate] = acc;
    }
    __syncthreads();
    int t = threadIdx.x;
    if (t < 7) {
        int r2 = bid * 7 + t;
        if (r2 < H) {
            float gi = sm.gate[t * 4 + 0] + bih[r2        ] + bhh[r2        ];
            float gf = sm.gate[t * 4 + 1] + bih[r2 +     H] + bhh[r2 +     H];
            float gg = sm.gate[t * 4 + 2] + bih[r2 + 2 * H] + bhh[r2 + 2 * H];
            float go = sm.gate[t * 4 + 3] + bih[r2 + 3 * H] + bhh[r2 + 3 * H];
            float c  = sigm(gf) * cprev[r2] + sigm(gi) * tanhf(gg);
            cout[r2] = c;
            hout[r2] = sigm(go) * tanhf(c);
        }
    }
}

// ---------------- the megakernel ----------------
__global__ void __launch_bounds__(NT, 1) decoder_mega(
    const float* __restrict__ enc, const int* __restrict__ word,
    const float* __restrict__ h0,  const float* __restrict__ c0,
    const float* __restrict__ emb,
    const float* __restrict__ wih, const float* __restrict__ whh,
    const float* __restrict__ bih, const float* __restrict__ bhh,
    const float* __restrict__ a1w, const float* __restrict__ a1b,
    const float* __restrict__ a2w, const float* __restrict__ a2b,
    const float* __restrict__ f1w, const float* __restrict__ f1b,
    const float* __restrict__ f2w, const float* __restrict__ f2b,
    float* __restrict__ dout, int S)
{
    __shared__ Shm sm;
    const int tid = threadIdx.x, lane = tid & 31, wid = tid >> 5;
    const int bid = blockIdx.x;
    const int gw  = bid * 32 + wid;
    const float Sf = (float)S;

    float* y    = dout;              // [V]
    float* fco  = y   + V;           // [H]
    float* hn   = fco + H;           // [2,H]
    float* cn   = hn  + 2 * H;       // [2,H]
    float* aout = cn  + 2 * H;       // [WIN]

    // ---- phase 0: LSTM layer 0 (x = embedding[word]) ----
    {
        const float4* x4 = (const float4*)(emb + (size_t)word[0] * H);
        const float4* h4 = (const float4*)h0;
        lstm_layer(x4, h4, c0, wih, whh, bih, bhh, hn, cn, bid, wid, lane, sm);
    }
    gbar();

    // ---- phase 1: LSTM layer 1 (x = h of layer 0) ----
    {
        const float4* x4 = (const float4*)hn;
        const float4* h4 = (const float4*)(h0 + H);
        lstm_layer(x4, h4, c0 + H, wih + 4 * H * H, whh + 4 * H * H,
                   bih + 4 * H, bhh + 4 * H, hn + H, cn + H, bid, wid, lane, sm);
    }
    gbar();

    const float* ht = hn + H;
    const float4* ht4 = (const float4*)ht;

    // ---- phase 2: att_fc1 (512 rows) + full-sequence scores + scratch reset ----
    if (gw < HH2) {
        const float4* w4 = (const float4*)a1w + (size_t)gw * H4;
        float acc = 0.f;
        #pragma unroll
        for (int k = 0; k < 8; k++) { int i = lane + 32 * k; acc += dot4(w4[i], ht4[i]); }
        acc = warpSum(acc);
        if (lane == 0) g_t1[gw] = tanhf(acc + a1b[gw]);
    } else {
        int s = gw - HH2;
        int slim = (S < SMAX) ? S : SMAX;
        if (s < slim) {
            const float4* e4 = (const float4*)(enc + (size_t)s * H);
            float acc = 0.f;
            #pragma unroll
            for (int k = 0; k < 8; k++) { int i = lane + 32 * k; acc += dot4(e4[i], ht4[i]); }
            acc = warpSum(acc);
            if (lane == 0) g_sc[s] = acc;
        }
    }
    if (bid == NB - 1) g_ctx[tid] = 0.f;
    gbar();

    // ---- phase 3: redundant p + window softmax; distributed ctx ----
    {
        float part = (tid < HH2) ? g_t1[tid] * a2w[tid] : 0.f;
        part = warpSum(part);
        if (lane == 0) sm.red[wid] = part;
        __syncthreads();
        if (tid == 0) {
            float s = a2b[0];
            #pragma unroll
            for (int i = 0; i < 32; i++) s += sm.red[i];
            float p = Sf * sigm(s);
            sm.p  = p;
            sm.ws = (int)rintf(fmaxf(p - 64.f, 0.f));
            sm.we = (int)rintf(fminf(p + 64.f, Sf - 1.f));
        }
        __syncthreads();
        int ws = sm.ws, we = sm.we;
        if (tid < WIN) {
            int idx = ws + tid;
            int ic  = min(idx, S - 1);
            sm.sarr[tid] = (idx <= we) ? g_sc[ic] : NEG;
        }
        __syncthreads();
        if (tid < 32) {
            float m = NEG;
            for (int i = lane; i < WIN; i += 32) m = fmaxf(m, sm.sarr[i]);
            m = warpMax(m);
            float e = 0.f;
            for (int i = lane; i < WIN; i += 32) e += expf(sm.sarr[i] - m);
            e = warpSum(e);
            if (lane == 0) { sm.mx = m; sm.sum = e; }
        }
        __syncthreads();
        if (tid < WIN) {
            int idx = ws + tid;
            float a = expf(sm.sarr[tid] - sm.mx) / sm.sum;
            float gss = expf(((float)idx - sm.p) * (1.f / 2048.f));
            a = (idx <= we) ? a * gss : 0.f;
            sm.aarr[tid] = a;
            if (bid == 0) aout[tid] = a;
        }
        __syncthreads();
        if (bid < WIN) {                 // block b accumulates window row b
            float a = sm.aarr[bid];
            int idx = min(sm.ws + bid, S - 1);
            atomicAdd(&g_ctx[tid], a * enc[(size_t)idx * H + tid]);
        }
    }
    gbar();

    // ---- phase 4: fc1 (1024 rows x 2048), rows spread over all blocks ----
    {
        int r = wid * NB + bid;
        if (wid < 7 && r < H) {
            const float4* w4 = (const float4*)f1w + (size_t)r * (2 * H4);
            const float4* c4 = (const float4*)g_ctx;
            float acc = 0.f;
            #pragma unroll
            for (int k = 0; k < 8; k++) { int i = lane + 32 * k; acc += dot4(w4[i      ], c4[i]); }
            #pragma unroll
            for (int k = 0; k < 8; k++) { int i = lane + 32 * k; acc += dot4(w4[i + 256], ht4[i]); }
            acc = warpSum(acc);
            if (lane == 0) fco[r] = tanhf(acc + f1b[r]);
        }
    }
    gbar();

    // ---- phase 5: fc2 — per-block contiguous 217-row chunk; logits kept in
    //      shared; fused in-block (max,expsum). Small resident head (normal
    //      LDG) + streaming tail (__ldcs) preserves the L2-retained set. ----
    {
        const float4* x4 = (const float4*)fco;
        const int R0   = bid * CHUNK;
        const int Rend = min(R0 + CHUNK, V);
        if (wid < 31) {
            #pragma unroll 1
            for (int j = 0; j < 7; j++) {
                int r = R0 + wid * 7 + j;
                if (r < Rend) {
                    const float4* w4 = (const float4*)f2w + (size_t)r * H4;
                    float acc = 0.f;
                    if (r < FC2_HEAD) {
                        #pragma unroll
                        for (int k = 0; k < 8; k++) {
                            int i = lane + 32 * k;
                            acc += dot4(w4[i], x4[i]);
                        }
                    } else {
                        #pragma unroll
                        for (int k = 0; k < 8; k++) {
                            int i = lane + 32 * k;
                            acc += dot4(__ldcs(w4 + i), x4[i]);
                        }
                    }
                    acc = warpSum(acc);
                    if (lane == 0) sm.lv[r - R0] = acc + f2b[r];
                }
            }
        }
        __syncthreads();

        // in-block (max, expsum) over this chunk's logits
        int n = Rend - R0;
        float v = (tid < n) ? sm.lv[tid] : NEG;
        float m = warpMax(v);
        if (lane == 0) sm.red[wid] = m;
        __syncthreads();
        if (tid == 0) {
            float mm = sm.red[0];
            #pragma unroll
            for (int k = 1; k < 32; k++) mm = fmaxf(mm, sm.red[k]);
            sm.mx = mm;
        }
        __syncthreads();
        float mx = sm.mx;
        float e = (tid < n) ? expf(v - mx) : 0.f;
        e = warpSum(e);
        __syncthreads();
        if (lane == 0) sm.red[wid] = e;
        __syncthreads();
        if (tid == 0) {
            float ss = 0.f;
            #pragma unroll
            for (int k = 0; k < 32; k++) ss += sm.red[k];
            g_pm[bid] = mx; g_ps[bid] = ss;
        }
    }
    gbar();

    // ---- phase 6: combine 148 partials (fixed tree); write y = v - lse ----
    {
        if (tid < 256) {
            if (tid < NB) { sm.mr[tid] = g_pm[tid]; sm.sr[tid] = g_ps[tid]; }
            else          { sm.mr[tid] = NEG;       sm.sr[tid] = 0.f; }
        }
        __syncthreads();
        for (int off = 128; off > 0; off >>= 1) {
            if (tid < off) {
                float m1 = sm.mr[tid], m2 = sm.mr[tid + off];
                float m = fmaxf(m1, m2);
                sm.sr[tid] = sm.sr[tid] * expf(m1 - m) + sm.sr[tid + off] * expf(m2 - m);
                sm.mr[tid] = m;
            }
            __syncthreads();
        }
        float lse = sm.mr[0] + logf(sm.sr[0]);
        const int R0   = bid * CHUNK;
        const int n    = min(R0 + CHUNK, V) - R0;
        if (tid < n) y[R0 + tid] = sm.lv[tid] - lse;
    }
}

// ---------------- launch ----------------
extern "C" void kernel_launch(void* const* d_in, const int* in_sizes, int n_in,
                              void* d_out, int out_size)
{
    const float* enc  = (const float*)d_in[1];
    const int*   word = (const int*)  d_in[2];
    const float* h0   = (const float*)d_in[3];
    const float* c0   = (const float*)d_in[4];
    const float* emb  = (const float*)d_in[5];
    const float* wih  = (const float*)d_in[6];
    const float* whh  = (const float*)d_in[7];
    const float* bih  = (const float*)d_in[8];
    const float* bhh  = (const float*)d_in[9];
    const float* a1w  = (const float*)d_in[10];
    const float* a1b  = (const float*)d_in[11];
    const float* a2w  = (const float*)d_in[12];
    const float* a2b  = (const float*)d_in[13];
    const float* f1w  = (const float*)d_in[14];
    const float* f1b  = (const float*)d_in[15];
    const float* f2w  = (const float*)d_in[16];
    const float* f2b  = (const float*)d_in[17];

    int S = in_sizes[1] / H;

    decoder_mega<<<NB, NT>>>(enc, word, h0, c0, emb, wih, whh, bih, bhh,
                             a1w, a1b, a2w, a2b, f1w, f1b, f2w, f2b,
                             (float*)d_out, S);
}

// round 14
// speedup vs baseline: 1.1716x; 1.0347x over previous
#include <cuda_runtime.h>
#include <math.h>

#define H      1024
#define H4     (H/4)          // 256 float4 per H row
#define HH2    512
#define V      32000
#define WIN    129
#define NB     148
#define NT     1024
#define NWRP   (NB * 32)       // 4736 warps
#define SMAX   4096
#define NEG    -1e30f
#define CHUNK  217             // ceil(V/NB); 31 warps x 7 rows

// ---------------- persistent scratch (no allocation allowed) ----------------
__device__ float g_t1[HH2];          // tanh(att_fc1)
__device__ float g_sc[SMAX];         // full-sequence raw scores
__device__ float g_ctx[H];           // attention context (atomicAdd target)
__device__ float g_pm[NB];           // per-block logit max
__device__ float g_ps[NB];           // per-block logit expsum
__device__ float g_dummy;            // DCE sink for prefetch loads
__device__ unsigned g_cnt;           // barrier arrival counter
__device__ volatile unsigned g_sense;// barrier sense flag

// ---------------- helpers ----------------
__device__ __forceinline__ float dot4(float4 a, float4 b) {
    return fmaf(a.x, b.x, fmaf(a.y, b.y, fmaf(a.z, b.z, a.w * b.w)));
}
__device__ __forceinline__ float warpSum(float v) {
    #pragma unroll
    for (int o = 16; o > 0; o >>= 1) v += __shfl_xor_sync(0xffffffffu, v, o);
    return v;
}
__device__ __forceinline__ float warpMax(float v) {
    #pragma unroll
    for (int o = 16; o > 0; o >>= 1) v = fmaxf(v, __shfl_xor_sync(0xffffffffu, v, o));
    return v;
}
__device__ __forceinline__ float sigm(float x) { return 1.f / (1.f + expf(-x)); }

// Stream `nrows` fc2 rows (from row r0) into L2 at EVICT-FIRST priority by
// reading every sector with __ldcs and discarding. Cannot displace the
// normal-priority retained set (unlike prefetch.global.L2 — see R11).
__device__ __forceinline__ void pf_rows_cs(const float* __restrict__ f2w,
                                           int r0, int nrows, int lane)
{
    const float4* p = (const float4*)f2w + (size_t)r0 * H4;
    float acc = 0.f;
    for (int rr = 0; rr < nrows; rr++) {
        #pragma unroll
        for (int k = 0; k < 8; k++)
            acc += __ldcs((const float*)(p + (size_t)rr * H4 + k * 32 + lane));
    }
    if (acc == 1.2345e38f) g_dummy = acc;   // never true; defeats DCE
}

// ---------------- grid barrier (sense-reversing, all NB blocks) ----------------
__device__ __forceinline__ void gbar() {
    __syncthreads();
    if (threadIdx.x == 0) {
        unsigned my = g_sense;                 // volatile read
        __threadfence();                       // release prior writes
        if (atomicAdd(&g_cnt, 1u) == NB - 1u) {
            atomicExch(&g_cnt, 0u);            // reset for next barrier
            __threadfence();
            g_sense = my ^ 1u;                 // release
        } else {
            while (g_sense == my) { }          // volatile poll
            __threadfence();                   // acquire
        }
    }
    __syncthreads();
}

struct Shm {
    float gate[28];      // 7 rows x 4 gates
    float red[32];
    float sarr[WIN];
    float aarr[WIN];
    float mr[256];
    float sr[256];
    float lv[CHUNK];     // this block's raw logits
    float p;
    int   ws, we;
    float mx, sum;
};

// ---------------- LSTM layer: 28 warps/block, 4 gate-warps per row.
// Warps 28-31 (idle for the matvec) stream this block's fc2 chunk head
// into L2 evict-first to fill the otherwise-idle DRAM window on replays. ----
__device__ __forceinline__ void lstm_layer(
    const float4* __restrict__ x4, const float4* __restrict__ h4,
    const float* __restrict__ cprev,
    const float* __restrict__ wih, const float* __restrict__ whh,
    const float* __restrict__ bih, const float* __restrict__ bhh,
    float* __restrict__ hout, float* __restrict__ cout,
    const float* __restrict__ f2w, int pfbase,
    int bid, int wid, int lane, Shm& sm)
{
    int q = wid >> 2;            // local row 0..7
    int gate = wid & 3;
    int r = bid * 7 + q;
    if (q < 7 && r < H) {
        const float4* wi = (const float4*)wih + ((size_t)gate * H + r) * H4;
        const float4* wh = (const float4*)whh + ((size_t)gate * H + r) * H4;
        float acc = 0.f;
        #pragma unroll
        for (int k = 0; k < 8; k++) {
            int i = lane + 32 * k;
            acc += dot4(wi[i], x4[i]) + dot4(wh[i], h4[i]);
        }
        acc = warpSum(acc);
        if (lane == 0) sm.gate[q * 4 + gate] = acc;
    } else if (q == 7) {
        pf_rows_cs(f2w, pfbase + (wid - 28) * 4, 4, lane);   // 4 rows per idle warp
    }
    __syncthreads();
    int t = threadIdx.x;
    if (t < 7) {
        int r2 = bid * 7 + t;
        if (r2 < H) {
            float gi = sm.gate[t * 4 + 0] + bih[r2        ] + bhh[r2        ];
            float gf = sm.gate[t * 4 + 1] + bih[r2 +     H] + bhh[r2 +     H];
            float gg = sm.gate[t * 4 + 2] + bih[r2 + 2 * H] + bhh[r2 + 2 * H];
            float go = sm.gate[t * 4 + 3] + bih[r2 + 3 * H] + bhh[r2 + 3 * H];
            float c  = sigm(gf) * cprev[r2] + sigm(gi) * tanhf(gg);
            cout[r2] = c;
            hout[r2] = sigm(go) * tanhf(c);
        }
    }
}

// ---------------- the megakernel ----------------
__global__ void __launch_bounds__(NT, 1) decoder_mega(
    const float* __restrict__ enc, const int* __restrict__ word,
    const float* __restrict__ h0,  const float* __restrict__ c0,
    const float* __restrict__ emb,
    const float* __restrict__ wih, const float* __restrict__ whh,
    const float* __restrict__ bih, const float* __restrict__ bhh,
    const float* __restrict__ a1w, const float* __restrict__ a1b,
    const float* __restrict__ a2w, const float* __restrict__ a2b,
    const float* __restrict__ f1w, const float* __restrict__ f1b,
    const float* __restrict__ f2w, const float* __restrict__ f2b,
    float* __restrict__ dout, int S)
{
    __shared__ Shm sm;
    const int tid = threadIdx.x, lane = tid & 31, wid = tid >> 5;
    const int bid = blockIdx.x;
    const int gw  = bid * 32 + wid;
    const float Sf = (float)S;
    const int R0  = bid * CHUNK;           // this block's fc2 chunk

    float* y    = dout;              // [V]
    float* fco  = y   + V;           // [H]
    float* hn   = fco + H;           // [2,H]
    float* cn   = hn  + 2 * H;       // [2,H]
    float* aout = cn  + 2 * H;       // [WIN]

    // ---- phase 0: LSTM layer 0 (x = embedding[word]); prefetch chunk rows 0-15 ----
    {
        const float4* x4 = (const float4*)(emb + (size_t)word[0] * H);
        const float4* h4 = (const float4*)h0;
        lstm_layer(x4, h4, c0, wih, whh, bih, bhh, hn, cn,
                   f2w, R0, bid, wid, lane, sm);
    }
    gbar();

    // ---- phase 1: LSTM layer 1 (x = h of layer 0); prefetch chunk rows 16-31 ----
    {
        const float4* x4 = (const float4*)hn;
        const float4* h4 = (const float4*)(h0 + H);
        lstm_layer(x4, h4, c0 + H, wih + 4 * H * H, whh + 4 * H * H,
                   bih + 4 * H, bhh + 4 * H, hn + H, cn + H,
                   f2w, R0 + 16, bid, wid, lane, sm);
    }
    gbar();

    const float* ht = hn + H;
    const float4* ht4 = (const float4*)ht;

    // ---- phase 2: att_fc1 (512 rows) + full-sequence scores + scratch reset ----
    if (gw < HH2) {
        const float4* w4 = (const float4*)a1w + (size_t)gw * H4;
        float acc = 0.f;
        #pragma unroll
        for (int k = 0; k < 8; k++) { int i = lane + 32 * k; acc += dot4(w4[i], ht4[i]); }
        acc = warpSum(acc);
        if (lane == 0) g_t1[gw] = tanhf(acc + a1b[gw]);
    } else {
        int s = gw - HH2;
        int slim = (S < SMAX) ? S : SMAX;
        if (s < slim) {
            const float4* e4 = (const float4*)(enc + (size_t)s * H);
            float acc = 0.f;
            #pragma unroll
            for (int k = 0; k < 8; k++) { int i = lane + 32 * k; acc += dot4(e4[i], ht4[i]); }
            acc = warpSum(acc);
            if (lane == 0) g_sc[s] = acc;
        }
    }
    if (bid == NB - 1) g_ctx[tid] = 0.f;
    gbar();

    // ---- phase 3: redundant p + window softmax; distributed ctx ----
    {
        float part = (tid < HH2) ? g_t1[tid] * a2w[tid] : 0.f;
        part = warpSum(part);
        if (lane == 0) sm.red[wid] = part;
        __syncthreads();
        if (tid == 0) {
            float s = a2b[0];
            #pragma unroll
            for (int i = 0; i < 32; i++) s += sm.red[i];
            float p = Sf * sigm(s);
            sm.p  = p;
            sm.ws = (int)rintf(fmaxf(p - 64.f, 0.f));
            sm.we = (int)rintf(fminf(p + 64.f, Sf - 1.f));
        }
        __syncthreads();
        int ws = sm.ws, we = sm.we;
        if (tid < WIN) {
            int idx = ws + tid;
            int ic  = min(idx, S - 1);
            sm.sarr[tid] = (idx <= we) ? g_sc[ic] : NEG;
        }
        __syncthreads();
        if (tid < 32) {
            float m = NEG;
            for (int i = lane; i < WIN; i += 32) m = fmaxf(m, sm.sarr[i]);
            m = warpMax(m);
            float e = 0.f;
            for (int i = lane; i < WIN; i += 32) e += expf(sm.sarr[i] - m);
            e = warpSum(e);
            if (lane == 0) { sm.mx = m; sm.sum = e; }
        }
        __syncthreads();
        if (tid < WIN) {
            int idx = ws + tid;
            float a = expf(sm.sarr[tid] - sm.mx) / sm.sum;
            float gss = expf(((float)idx - sm.p) * (1.f / 2048.f));
            a = (idx <= we) ? a * gss : 0.f;
            sm.aarr[tid] = a;
            if (bid == 0) aout[tid] = a;
        }
        __syncthreads();
        if (bid < WIN) {                 // block b accumulates window row b
            float a = sm.aarr[bid];
            int idx = min(sm.ws + bid, S - 1);
            atomicAdd(&g_ctx[tid], a * enc[(size_t)idx * H + tid]);
        }
    }
    gbar();

    // ---- phase 4: fc1 (1024 rows x 2048); idle warps 8-15 prefetch rows 32-39 ----
    {
        int r = wid * NB + bid;
        if (wid < 7 && r < H) {
            const float4* w4 = (const float4*)f1w + (size_t)r * (2 * H4);
            const float4* c4 = (const float4*)g_ctx;
            float acc = 0.f;
            #pragma unroll
            for (int k = 0; k < 8; k++) { int i = lane + 32 * k; acc += dot4(w4[i      ], c4[i]); }
            #pragma unroll
            for (int k = 0; k < 8; k++) { int i = lane + 32 * k; acc += dot4(w4[i + 256], ht4[i]); }
            acc = warpSum(acc);
            if (lane == 0) fco[r] = tanhf(acc + f1b[r]);
        } else if (wid >= 8 && wid < 16) {
            pf_rows_cs(f2w, R0 + 32 + (wid - 8), 1, lane);
        }
    }
    gbar();

    // ---- phase 5: fc2 — per-block contiguous 217-row chunk; all __ldcs;
    //      logits in shared; fused in-block (max,expsum). ----
    {
        const float4* x4 = (const float4*)fco;
        const int Rend = min(R0 + CHUNK, V);
        if (wid < 31) {
            #pragma unroll 1
            for (int j = 0; j < 7; j++) {
                int r = R0 + wid * 7 + j;
                if (r < Rend) {
                    const float4* w4 = (const float4*)f2w + (size_t)r * H4;
                    float acc = 0.f;
                    #pragma unroll
                    for (int k = 0; k < 8; k++) {
                        int i = lane + 32 * k;
                        acc += dot4(__ldcs(w4 + i), x4[i]);
                    }
                    acc = warpSum(acc);
                    if (lane == 0) sm.lv[r - R0] = acc + f2b[r];
                }
            }
        }
        __syncthreads();

        // in-block (max, expsum) over this chunk's logits
        int n = Rend - R0;
        float v = (tid < n) ? sm.lv[tid] : NEG;
        float m = warpMax(v);
        if (lane == 0) sm.red[wid] = m;
        __syncthreads();
        if (tid == 0) {
            float mm = sm.red[0];
            #pragma unroll
            for (int k = 1; k < 32; k++) mm = fmaxf(mm, sm.red[k]);
            sm.mx = mm;
        }
        __syncthreads();
        float mx = sm.mx;
        float e = (tid < n) ? expf(v - mx) : 0.f;
        e = warpSum(e);
        __syncthreads();
        if (lane == 0) sm.red[wid] = e;
        __syncthreads();
        if (tid == 0) {
            float ss = 0.f;
            #pragma unroll
            for (int k = 0; k < 32; k++) ss += sm.red[k];
            g_pm[bid] = mx; g_ps[bid] = ss;
        }
    }
    gbar();

    // ---- phase 6: combine 148 partials (fixed tree); write y = v - lse ----
    {
        if (tid < 256) {
            if (tid < NB) { sm.mr[tid] = g_pm[tid]; sm.sr[tid] = g_ps[tid]; }
            else          { sm.mr[tid] = NEG;       sm.sr[tid] = 0.f; }
        }
        __syncthreads();
        for (int off = 128; off > 0; off >>= 1) {
            if (tid < off) {
                float m1 = sm.mr[tid], m2 = sm.mr[tid + off];
                float m = fmaxf(m1, m2);
                sm.sr[tid] = sm.sr[tid] * expf(m1 - m) + sm.sr[tid + off] * expf(m2 - m);
                sm.mr[tid] = m;
            }
            __syncthreads();
        }
        float lse = sm.mr[0] + logf(sm.sr[0]);
        const int n = min(R0 + CHUNK, V) - R0;
        if (tid < n) y[R0 + tid] = sm.lv[tid] - lse;
    }
}

// ---------------- launch ----------------
extern "C" void kernel_launch(void* const* d_in, const int* in_sizes, int n_in,
                              void* d_out, int out_size)
{
    const float* enc  = (const float*)d_in[1];
    const int*   word = (const int*)  d_in[2];
    const float* h0   = (const float*)d_in[3];
    const float* c0   = (const float*)d_in[4];
    const float* emb  = (const float*)d_in[5];
    const float* wih  = (const float*)d_in[6];
    const float* whh  = (const float*)d_in[7];
    const float* bih  = (const float*)d_in[8];
    const float* bhh  = (const float*)d_in[9];
    const float* a1w  = (const float*)d_in[10];
    const float* a1b  = (const float*)d_in[11];
    const float* a2w  = (const float*)d_in[12];
    const float* a2b  = (const float*)d_in[13];
    const float* f1w  = (const float*)d_in[14];
    const float* f1b  = (const float*)d_in[15];
    const float* f2w  = (const float*)d_in[16];
    const float* f2b  = (const float*)d_in[17];

    int S = in_sizes[1] / H;

    decoder_mega<<<NB, NT>>>(enc, word, h0, c0, emb, wih, whh, bih, bhh,
                             a1w, a1b, a2w, a2b, f1w, f1b, f2w, f2b,
                             (float*)d_out, S);
}